// round 11
// baseline (speedup 1.0000x reference)
#include <cuda_runtime.h>
#include <cuda_fp16.h>
#include <cstdint>
#include <cstddef>

#define BSZ  1024
#define HD   1024
#define VOUT 50000
#define VINP 32000
#define SRCN 256

#define BM 128
#define BN 128
#define BK 32
#define NCH (HD / BK)            // 32 K-chunks
#define NSTAGE 4

// smem rows padded to 80B (20 words): 8 consecutive rows x 4 words = 32 banks
#define ROWB 80
#define TILEB (128 * ROWB)       // 10240 B per tile
#define OFF_A 0
#define OFF_B (TILEB)
#define STAGE_BYTES (2 * TILEB)  // 20480
#define SMEM_TOTAL (NSTAGE * STAGE_BYTES)   // 81920

// ---------------- scratch (static device globals) ---------------------------
__device__ __half g_Wf[(size_t)VOUT * HD];
__device__ __half g_Xf[(size_t)BSZ * HD];
__device__ float g_b2[VOUT];
__device__ float g_G [(size_t)BSZ * VOUT];          // gen_scores -> out_scores
__device__ int   g_sel[VOUT];
__device__ int   g_win[VINP];

// ---------------- PTX helpers ------------------------------------------------
__device__ __forceinline__ uint32_t smem_u32(const void* p) {
    uint32_t a;
    asm("{ .reg .u64 t; cvta.to.shared.u64 t, %1; cvt.u32.u64 %0, t; }"
        : "=r"(a) : "l"(p));
    return a;
}

__device__ __forceinline__ void cp16(uint32_t dst, const void* src, int nbytes) {
    asm volatile("cp.async.cg.shared.global [%0], [%1], 16, %2;"
                 :: "r"(dst), "l"(src), "r"(nbytes) : "memory");
}
#define CP_COMMIT() asm volatile("cp.async.commit_group;" ::: "memory")
#define CP_WAIT(n)  asm volatile("cp.async.wait_group %0;" :: "n"(n) : "memory")

__device__ __forceinline__ void ldsm4(uint32_t* r, uint32_t addr) {
    asm volatile("ldmatrix.sync.aligned.m8n8.x4.shared.b16 {%0,%1,%2,%3}, [%4];"
                 : "=r"(r[0]), "=r"(r[1]), "=r"(r[2]), "=r"(r[3]) : "r"(addr));
}

__device__ __forceinline__ void mma_fp16(float* d, const uint32_t* a, const uint32_t* b) {
    asm volatile("mma.sync.aligned.m16n8k16.row.col.f32.f16.f16.f32 "
                 "{%0,%1,%2,%3}, {%4,%5,%6,%7}, {%8,%9}, {%0,%1,%2,%3};"
                 : "+f"(d[0]), "+f"(d[1]), "+f"(d[2]), "+f"(d[3])
                 : "r"(a[0]), "r"(a[1]), "r"(a[2]), "r"(a[3]),
                   "r"(b[0]), "r"(b[1]));
}

// ---------------- small prep kernels ----------------------------------------
__global__ void k_sel_init() {
    int i = blockIdx.x * 256 + threadIdx.x;
    if (i < VOUT) g_sel[i] = -1;
}
__global__ void k_sel_max(const int* __restrict__ i2a) {
    int i = blockIdx.x * 256 + threadIdx.x;
    if (i < VINP) atomicMax(&g_sel[i2a[i]], i);
}
__global__ void k_win_build(const int* __restrict__ i2a) {
    int i = blockIdx.x * 256 + threadIdx.x;
    if (i < VINP) {
        int a = i2a[i];
        g_win[i] = (g_sel[a] == i) ? a : -1;
    }
}

// permute W rows + convert fp32 -> fp16
__global__ void k_prep_w(const float* __restrict__ W, const float* __restrict__ bias,
                         const int* __restrict__ omap) {
    int j  = blockIdx.x;
    int om = omap[j];
    float4 v = ((const float4*)(W + (size_t)om * HD))[threadIdx.x];
    size_t o = (size_t)j * HD + threadIdx.x * 4;
    ((__half2*)(g_Wf + o))[0] = __floats2half2_rn(v.x, v.y);
    ((__half2*)(g_Wf + o))[1] = __floats2half2_rn(v.z, v.w);
    if (threadIdx.x == 0) g_b2[j] = bias[om];
}

__global__ void k_prep_x(const float* __restrict__ X) {
    int m = blockIdx.x;
    float4 v = ((const float4*)(X + (size_t)m * HD))[threadIdx.x];
    size_t o = (size_t)m * HD + threadIdx.x * 4;
    ((__half2*)(g_Xf + o))[0] = __floats2half2_rn(v.x, v.y);
    ((__half2*)(g_Xf + o))[1] = __floats2half2_rn(v.z, v.w);
}

// ---------------- mma.sync GEMM ----------------------------------------------
__device__ __forceinline__ void issue_stage(uint32_t sb, int stage, int kc,
                                            int m0, int n0, int tid) {
    uint32_t base = sb + stage * STAGE_BYTES;
    for (int i = tid; i < 512; i += 256) {     // 128 rows * 4 16B-segments
        int r = i >> 2, s = i & 3;
        uint32_t doff = r * ROWB + s * 16;
        size_t asrc = (size_t)(m0 + r) * HD + kc * BK + s * 8;
        cp16(base + OFF_A + doff, g_Xf + asrc, 16);
        int nr = n0 + r;
        int p  = (nr < VOUT) ? 16 : 0;         // 0 -> cp.async zero-fills
        size_t bsrc = (size_t)(nr < VOUT ? nr : (VOUT - 1)) * HD + kc * BK + s * 8;
        cp16(base + OFF_B + doff, g_Wf + bsrc, p);
    }
}

__global__ __launch_bounds__(256, 2)
void k_gemm(const int* __restrict__ mask, float* __restrict__ out2) {
    extern __shared__ char smem[];
    uint32_t sb = smem_u32(smem);
    const int tid  = threadIdx.x;
    const int wid  = tid >> 5;
    const int lane = tid & 31;
    const int wm   = wid >> 1;          // 0..3 -> m
    const int wn   = wid & 1;           // 0..1 -> n
    const int m0   = blockIdx.x * BM;   // 8 m-tiles, fastest -> W reuse in L2
    const int n0   = blockIdx.y * BN;   // 391 n-tiles

    float acc[2][8][4];
#pragma unroll
    for (int i = 0; i < 2; ++i)
#pragma unroll
        for (int j = 0; j < 8; ++j)
#pragma unroll
            for (int q2 = 0; q2 < 4; ++q2) acc[i][j][q2] = 0.f;

    // prologue: 3 chunk-loads in flight
    issue_stage(sb, 0, 0, m0, n0, tid); CP_COMMIT();
    issue_stage(sb, 1, 1, m0, n0, tid); CP_COMMIT();
    issue_stage(sb, 2, 2, m0, n0, tid); CP_COMMIT();

    // ldmatrix per-lane address offsets
    const int q    = lane >> 3;
    const int rsel = lane & 7;
    // A x4 tiles: (r,k0),(r+8,k0),(r,k0+8),(r+8,k0+8)
    const uint32_t a_off = (uint32_t)((wm * 32 + rsel + ((q & 1) << 3)) * ROWB + (q >> 1) * 16);
    // B x4 tiles: (j,k0),(j,k8),(j+1,k0),(j+1,k8)
    const uint32_t b_off = (uint32_t)((wn * 64 + rsel + ((q >> 1) << 3)) * ROWB + (q & 1) * 16);

    const int lr = lane >> 2;          // 0..7  (epilogue)
    const int lc = (lane & 3) * 2;     // 0,2,4,6

    for (int c = 0; c < NCH; ++c) {
        int s = c & (NSTAGE - 1);
        CP_WAIT(2);                    // oldest pending group (chunk c) complete
        __syncthreads();               // all warps done with buffer (c+3)&3's old data
        if (c + 3 < NCH) {
            issue_stage(sb, (s + 3) & (NSTAGE - 1), c + 3, m0, n0, tid);
            CP_COMMIT();
        }

        uint32_t stb = sb + s * STAGE_BYTES;
#pragma unroll
        for (int kk = 0; kk < 2; ++kk) {
            uint32_t kb = kk * 32;                 // 16 fp16 = 32 bytes
            uint32_t Af[2][4];
            uint32_t aA = stb + OFF_A + a_off + kb;
            ldsm4(Af[0], aA);
            ldsm4(Af[1], aA + 16 * ROWB);

#pragma unroll
            for (int jp = 0; jp < 4; ++jp) {       // j-pairs: (0,1)(2,3)(4,5)(6,7)
                uint32_t Bf[4];                    // [0,1]=j, [2,3]=j+1
                ldsm4(Bf, stb + OFF_B + b_off + kb + (uint32_t)(jp * 16 * ROWB));
                mma_fp16(acc[0][jp * 2    ], Af[0], Bf    );
                mma_fp16(acc[1][jp * 2    ], Af[1], Bf    );
                mma_fp16(acc[0][jp * 2 + 1], Af[0], Bf + 2);
                mma_fp16(acc[1][jp * 2 + 1], Af[1], Bf + 2);
            }
        }
    }

    // epilogue: bias add, write G and gen_masked
#pragma unroll
    for (int i = 0; i < 2; ++i) {
        int r0 = m0 + wm * 32 + i * 16 + lr;
#pragma unroll
        for (int j = 0; j < 8; ++j) {
            int n = n0 + wn * 64 + j * 8 + lc;
            if (n < VOUT) {
                float2 bb = *(const float2*)(g_b2 + n);
                float gx = acc[i][j][0] + bb.x;
                float gy = acc[i][j][1] + bb.y;
                size_t o0 = (size_t)r0 * VOUT + n;
                *(float2*)(g_G + o0) = make_float2(gx, gy);
                int2 mk0 = *(const int2*)(mask + o0);
                *(float2*)(out2 + o0) =
                    make_float2(gx - 1.0e6f * (float)mk0.x, gy - 1.0e6f * (float)mk0.y);

                float gz = acc[i][j][2] + bb.x;
                float gw = acc[i][j][3] + bb.y;
                size_t o1 = (size_t)(r0 + 8) * VOUT + n;
                *(float2*)(g_G + o1) = make_float2(gz, gw);
                int2 mk1 = *(const int2*)(mask + o1);
                *(float2*)(out2 + o1) =
                    make_float2(gz - 1.0e6f * (float)mk1.x, gw - 1.0e6f * (float)mk1.y);
            }
        }
    }
}

// ---------------- scatter pointer scores into G -----------------------------
__global__ void k_scatter(const float* __restrict__ attn, const int* __restrict__ ctx) {
    int b = blockIdx.x;
    int j = threadIdx.x;
    int v = ctx[b * SRCN + j];
    int o = g_win[v];
    if (o >= 0) atomicAdd(g_G + (size_t)b * VOUT + o, attn[b * SRCN + j]);
}

// ---------------- fused softmax: reduce + normalize (row stays in L2) -------
__global__ void k_softmax(float* __restrict__ out1) {
    int b = blockIdx.x;
    const float4* Gr = (const float4*)(g_G + (size_t)b * VOUT);
    float m = -3.4e38f, s = 0.f;
    for (int i = threadIdx.x; i < VOUT / 4; i += blockDim.x) {
        float4 v = Gr[i];
#define ONL(x)                                                   \
        if ((x) > m) { s = s * __expf(m - (x)) + 1.f; m = (x); } \
        else         { s += __expf((x) - m); }
        ONL(v.x) ONL(v.y) ONL(v.z) ONL(v.w)
#undef ONL
    }
    __shared__ float sm[256], ss[256];
    sm[threadIdx.x] = m;
    ss[threadIdx.x] = s;
    __syncthreads();
    for (int off = 128; off; off >>= 1) {
        if (threadIdx.x < off) {
            float m1 = sm[threadIdx.x], s1 = ss[threadIdx.x];
            float m2 = sm[threadIdx.x + off], s2 = ss[threadIdx.x + off];
            float M = fmaxf(m1, m2);
            sm[threadIdx.x] = M;
            ss[threadIdx.x] = s1 * __expf(m1 - M) + s2 * __expf(m2 - M);
        }
        __syncthreads();
    }
    float rm  = sm[0];
    float inv = 1.f / ss[0];
    float4* Or = (float4*)(out1 + (size_t)b * VOUT);
    for (int i = threadIdx.x; i < VOUT / 4; i += blockDim.x) {
        float4 v = Gr[i];                           // L2-resident re-read
        float4 o;
        o.x = __expf(v.x - rm) * inv;
        o.y = __expf(v.y - rm) * inv;
        o.z = __expf(v.z - rm) * inv;
        o.w = __expf(v.w - rm) * inv;
        Or[i] = o;
    }
}

// ---------------- launch ----------------------------------------------------
extern "C" void kernel_launch(void* const* d_in, const int* in_sizes, int n_in,
                              void* d_out, int out_size) {
    const float* x    = (const float*)d_in[0];
    const float* W    = (const float*)d_in[1];
    const float* bv   = (const float*)d_in[2];
    const float* attn = (const float*)d_in[3];
    const int*   ctx  = (const int*)d_in[4];
    const int*   i2a  = (const int*)d_in[5];
    const int*   omap = (const int*)d_in[6];
    const int*   mask = (const int*)d_in[7];

    float* out1 = (float*)d_out;                       // out_probs  [B, VOUT]
    float* out2 = out1 + (size_t)BSZ * VOUT;           // gen_masked [B, VOUT]

    cudaFuncSetAttribute(k_gemm, cudaFuncAttributeMaxDynamicSharedMemorySize, SMEM_TOTAL);

    // Order keeps k_gemm in ncu's captured slot (4th launch).
    k_prep_w<<<VOUT, 256>>>(W, bv, omap);              // 1
    k_prep_x<<<BSZ, 256>>>(x);                         // 2
    k_sel_init<<<(VOUT + 255) / 256, 256>>>();         // 3

    dim3 ggrid(BSZ / BM, (VOUT + BN - 1) / BN);        // 8 x 391, m fastest
    k_gemm<<<ggrid, 256, SMEM_TOTAL>>>(mask, out2);    // 4  <- profiled

    k_sel_max  <<<(VINP + 255) / 256, 256>>>(i2a);     // 5
    k_win_build<<<(VINP + 255) / 256, 256>>>(i2a);     // 6

    k_scatter<<<BSZ, SRCN>>>(attn, ctx);               // G becomes out_scores

    k_softmax<<<BSZ, 256>>>(out1);
}

// round 12
// speedup vs baseline: 1.0396x; 1.0396x over previous
#include <cuda_runtime.h>
#include <cuda_fp16.h>
#include <cstdint>
#include <cstddef>

#define BSZ  1024
#define HD   1024
#define VOUT 50000
#define VINP 32000
#define SRCN 256

#define BM 128
#define BN 128
#define BK 64
#define NCH (HD / BK)            // 16 K-chunks
#define NSTAGE 3

// smem rows padded to 144B (36 words): 8-row LDSM hits all 32 banks once
#define ROWB 144
#define TILEB (128 * ROWB)       // 18432 B per tile
#define OFF_A 0
#define OFF_B (TILEB)
#define STAGE_BYTES (2 * TILEB)  // 36864
#define SMEM_TOTAL (NSTAGE * STAGE_BYTES)   // 110592

// ---------------- scratch (static device globals) ---------------------------
__device__ __half g_Wf[(size_t)VOUT * HD];
__device__ __half g_Xf[(size_t)BSZ * HD];
__device__ float g_b2[VOUT];
__device__ float g_G [(size_t)BSZ * VOUT];          // gen_scores -> out_scores
__device__ int   g_sel[VOUT];
__device__ int   g_win[VINP];

// ---------------- PTX helpers ------------------------------------------------
__device__ __forceinline__ uint32_t smem_u32(const void* p) {
    uint32_t a;
    asm("{ .reg .u64 t; cvta.to.shared.u64 t, %1; cvt.u32.u64 %0, t; }"
        : "=r"(a) : "l"(p));
    return a;
}

__device__ __forceinline__ void cp16(uint32_t dst, const void* src, int nbytes) {
    asm volatile("cp.async.cg.shared.global [%0], [%1], 16, %2;"
                 :: "r"(dst), "l"(src), "r"(nbytes) : "memory");
}
#define CP_COMMIT() asm volatile("cp.async.commit_group;" ::: "memory")
#define CP_WAIT(n)  asm volatile("cp.async.wait_group %0;" :: "n"(n) : "memory")

__device__ __forceinline__ void ldsm4(uint32_t* r, uint32_t addr) {
    asm volatile("ldmatrix.sync.aligned.m8n8.x4.shared.b16 {%0,%1,%2,%3}, [%4];"
                 : "=r"(r[0]), "=r"(r[1]), "=r"(r[2]), "=r"(r[3]) : "r"(addr));
}

__device__ __forceinline__ void mma_fp16(float* d, const uint32_t* a, const uint32_t* b) {
    asm volatile("mma.sync.aligned.m16n8k16.row.col.f32.f16.f16.f32 "
                 "{%0,%1,%2,%3}, {%4,%5,%6,%7}, {%8,%9}, {%0,%1,%2,%3};"
                 : "+f"(d[0]), "+f"(d[1]), "+f"(d[2]), "+f"(d[3])
                 : "r"(a[0]), "r"(a[1]), "r"(a[2]), "r"(a[3]),
                   "r"(b[0]), "r"(b[1]));
}

// ---------------- small prep kernels ----------------------------------------
__global__ void k_sel_init() {
    int i = blockIdx.x * 256 + threadIdx.x;
    if (i < VOUT) g_sel[i] = -1;
}
__global__ void k_sel_max(const int* __restrict__ i2a) {
    int i = blockIdx.x * 256 + threadIdx.x;
    if (i < VINP) atomicMax(&g_sel[i2a[i]], i);
}
__global__ void k_win_build(const int* __restrict__ i2a) {
    int i = blockIdx.x * 256 + threadIdx.x;
    if (i < VINP) {
        int a = i2a[i];
        g_win[i] = (g_sel[a] == i) ? a : -1;
    }
}

// permute W rows + convert fp32 -> fp16
__global__ void k_prep_w(const float* __restrict__ W, const float* __restrict__ bias,
                         const int* __restrict__ omap) {
    int j  = blockIdx.x;
    int om = omap[j];
    float4 v = ((const float4*)(W + (size_t)om * HD))[threadIdx.x];
    size_t o = (size_t)j * HD + threadIdx.x * 4;
    ((__half2*)(g_Wf + o))[0] = __floats2half2_rn(v.x, v.y);
    ((__half2*)(g_Wf + o))[1] = __floats2half2_rn(v.z, v.w);
    if (threadIdx.x == 0) g_b2[j] = bias[om];
}

__global__ void k_prep_x(const float* __restrict__ X) {
    int m = blockIdx.x;
    float4 v = ((const float4*)(X + (size_t)m * HD))[threadIdx.x];
    size_t o = (size_t)m * HD + threadIdx.x * 4;
    ((__half2*)(g_Xf + o))[0] = __floats2half2_rn(v.x, v.y);
    ((__half2*)(g_Xf + o))[1] = __floats2half2_rn(v.z, v.w);
}

// ---------------- mma.sync GEMM ----------------------------------------------
__device__ __forceinline__ void issue_stage(uint32_t sb, int stage, int kc,
                                            int m0, int n0, int tid) {
    uint32_t base = sb + stage * STAGE_BYTES;
    for (int i = tid; i < 1024; i += 256) {    // 128 rows * 8 16B-segments
        int r = i >> 3, s = i & 7;
        uint32_t doff = r * ROWB + s * 16;
        size_t asrc = (size_t)(m0 + r) * HD + kc * BK + s * 8;
        cp16(base + OFF_A + doff, g_Xf + asrc, 16);
        int nr = n0 + r;
        int p  = (nr < VOUT) ? 16 : 0;         // 0 -> cp.async zero-fills
        size_t bsrc = (size_t)(nr < VOUT ? nr : (VOUT - 1)) * HD + kc * BK + s * 8;
        cp16(base + OFF_B + doff, g_Wf + bsrc, p);
    }
}

__global__ __launch_bounds__(256, 2)
void k_gemm(const int* __restrict__ mask, float* __restrict__ out2) {
    extern __shared__ char smem[];
    uint32_t sb = smem_u32(smem);
    const int tid  = threadIdx.x;
    const int wid  = tid >> 5;
    const int lane = tid & 31;
    const int wm   = wid >> 1;          // 0..3 -> m
    const int wn   = wid & 1;           // 0..1 -> n
    const int m0   = blockIdx.x * BM;   // 8 m-tiles, fastest -> W reuse in L2
    const int n0   = blockIdx.y * BN;   // 391 n-tiles

    float acc[2][8][4];
#pragma unroll
    for (int i = 0; i < 2; ++i)
#pragma unroll
        for (int j = 0; j < 8; ++j)
#pragma unroll
            for (int q2 = 0; q2 < 4; ++q2) acc[i][j][q2] = 0.f;

    // prologue: 2 chunk-loads in flight
    issue_stage(sb, 0, 0, m0, n0, tid); CP_COMMIT();
    issue_stage(sb, 1, 1, m0, n0, tid); CP_COMMIT();

    // ldmatrix per-lane address offsets
    const int q    = lane >> 3;
    const int rsel = lane & 7;
    // A x4 tiles: (r,k0),(r+8,k0),(r,k0+8),(r+8,k0+8)
    const uint32_t a_off = (uint32_t)((wm * 32 + rsel + ((q & 1) << 3)) * ROWB + (q >> 1) * 16);
    // B x4 tiles: (j,k0),(j,k8),(j+1,k0),(j+1,k8)
    const uint32_t b_off = (uint32_t)((wn * 64 + rsel + ((q >> 1) << 3)) * ROWB + (q & 1) * 16);

    const int lr = lane >> 2;          // 0..7  (epilogue)
    const int lc = (lane & 3) * 2;     // 0,2,4,6

    int stage = 0;
    for (int c = 0; c < NCH; ++c) {
        int s = stage;
        stage = (stage + 1 == NSTAGE) ? 0 : stage + 1;
        CP_WAIT(1);                    // chunk c complete (c+1 may still be in flight)
        __syncthreads();               // all warps done with the buffer being refilled
        if (c + 2 < NCH) {
            int s2 = (s + 2 >= NSTAGE) ? s + 2 - NSTAGE : s + 2;
            issue_stage(sb, s2, c + 2, m0, n0, tid);
            CP_COMMIT();
        }

        uint32_t stb = sb + s * STAGE_BYTES;
#pragma unroll
        for (int kk = 0; kk < 4; ++kk) {
            uint32_t kb = kk * 32;                 // 16 fp16 = 32 bytes
            uint32_t Af[2][4];
            uint32_t aA = stb + OFF_A + a_off + kb;
            ldsm4(Af[0], aA);
            ldsm4(Af[1], aA + 16 * ROWB);

#pragma unroll
            for (int jp = 0; jp < 4; ++jp) {       // j-pairs: (0,1)(2,3)(4,5)(6,7)
                uint32_t Bf[4];                    // [0,1]=j, [2,3]=j+1
                ldsm4(Bf, stb + OFF_B + b_off + kb + (uint32_t)(jp * 16 * ROWB));
                mma_fp16(acc[0][jp * 2    ], Af[0], Bf    );
                mma_fp16(acc[1][jp * 2    ], Af[1], Bf    );
                mma_fp16(acc[0][jp * 2 + 1], Af[0], Bf + 2);
                mma_fp16(acc[1][jp * 2 + 1], Af[1], Bf + 2);
            }
        }
    }

    // epilogue: bias add, write G and gen_masked
#pragma unroll
    for (int i = 0; i < 2; ++i) {
        int r0 = m0 + wm * 32 + i * 16 + lr;
#pragma unroll
        for (int j = 0; j < 8; ++j) {
            int n = n0 + wn * 64 + j * 8 + lc;
            if (n < VOUT) {
                float2 bb = *(const float2*)(g_b2 + n);
                float gx = acc[i][j][0] + bb.x;
                float gy = acc[i][j][1] + bb.y;
                size_t o0 = (size_t)r0 * VOUT + n;
                *(float2*)(g_G + o0) = make_float2(gx, gy);
                int2 mk0 = *(const int2*)(mask + o0);
                *(float2*)(out2 + o0) =
                    make_float2(gx - 1.0e6f * (float)mk0.x, gy - 1.0e6f * (float)mk0.y);

                float gz = acc[i][j][2] + bb.x;
                float gw = acc[i][j][3] + bb.y;
                size_t o1 = (size_t)(r0 + 8) * VOUT + n;
                *(float2*)(g_G + o1) = make_float2(gz, gw);
                int2 mk1 = *(const int2*)(mask + o1);
                *(float2*)(out2 + o1) =
                    make_float2(gz - 1.0e6f * (float)mk1.x, gw - 1.0e6f * (float)mk1.y);
            }
        }
    }
}

// ---------------- scatter pointer scores into G -----------------------------
__global__ void k_scatter(const float* __restrict__ attn, const int* __restrict__ ctx) {
    int b = blockIdx.x;
    int j = threadIdx.x;
    int v = ctx[b * SRCN + j];
    int o = g_win[v];
    if (o >= 0) atomicAdd(g_G + (size_t)b * VOUT + o, attn[b * SRCN + j]);
}

// ---------------- fused softmax: reduce + normalize (row stays in L2) -------
__global__ void k_softmax(float* __restrict__ out1) {
    int b = blockIdx.x;
    const float4* Gr = (const float4*)(g_G + (size_t)b * VOUT);
    float m = -3.4e38f, s = 0.f;
    for (int i = threadIdx.x; i < VOUT / 4; i += blockDim.x) {
        float4 v = Gr[i];
#define ONL(x)                                                   \
        if ((x) > m) { s = s * __expf(m - (x)) + 1.f; m = (x); } \
        else         { s += __expf((x) - m); }
        ONL(v.x) ONL(v.y) ONL(v.z) ONL(v.w)
#undef ONL
    }
    __shared__ float sm[256], ss[256];
    sm[threadIdx.x] = m;
    ss[threadIdx.x] = s;
    __syncthreads();
    for (int off = 128; off; off >>= 1) {
        if (threadIdx.x < off) {
            float m1 = sm[threadIdx.x], s1 = ss[threadIdx.x];
            float m2 = sm[threadIdx.x + off], s2 = ss[threadIdx.x + off];
            float M = fmaxf(m1, m2);
            sm[threadIdx.x] = M;
            ss[threadIdx.x] = s1 * __expf(m1 - M) + s2 * __expf(m2 - M);
        }
        __syncthreads();
    }
    float rm  = sm[0];
    float inv = 1.f / ss[0];
    float4* Or = (float4*)(out1 + (size_t)b * VOUT);
    for (int i = threadIdx.x; i < VOUT / 4; i += blockDim.x) {
        float4 v = Gr[i];                           // L2-resident re-read
        float4 o;
        o.x = __expf(v.x - rm) * inv;
        o.y = __expf(v.y - rm) * inv;
        o.z = __expf(v.z - rm) * inv;
        o.w = __expf(v.w - rm) * inv;
        Or[i] = o;
    }
}

// ---------------- launch ----------------------------------------------------
extern "C" void kernel_launch(void* const* d_in, const int* in_sizes, int n_in,
                              void* d_out, int out_size) {
    const float* x    = (const float*)d_in[0];
    const float* W    = (const float*)d_in[1];
    const float* bv   = (const float*)d_in[2];
    const float* attn = (const float*)d_in[3];
    const int*   ctx  = (const int*)d_in[4];
    const int*   i2a  = (const int*)d_in[5];
    const int*   omap = (const int*)d_in[6];
    const int*   mask = (const int*)d_in[7];

    float* out1 = (float*)d_out;                       // out_probs  [B, VOUT]
    float* out2 = out1 + (size_t)BSZ * VOUT;           // gen_masked [B, VOUT]

    cudaFuncSetAttribute(k_gemm, cudaFuncAttributeMaxDynamicSharedMemorySize, SMEM_TOTAL);

    // Order keeps k_gemm in ncu's captured slot (4th launch).
    k_prep_w<<<VOUT, 256>>>(W, bv, omap);              // 1
    k_prep_x<<<BSZ, 256>>>(x);                         // 2
    k_sel_init<<<(VOUT + 255) / 256, 256>>>();         // 3

    dim3 ggrid(BSZ / BM, (VOUT + BN - 1) / BN);        // 8 x 391, m fastest
    k_gemm<<<ggrid, 256, SMEM_TOTAL>>>(mask, out2);    // 4  <- profiled

    k_sel_max  <<<(VINP + 255) / 256, 256>>>(i2a);     // 5
    k_win_build<<<(VINP + 255) / 256, 256>>>(i2a);     // 6

    k_scatter<<<BSZ, SRCN>>>(attn, ctx);               // G becomes out_scores

    k_softmax<<<BSZ, 256>>>(out1);
}

// round 15
// speedup vs baseline: 1.0513x; 1.0112x over previous
#include <cuda_runtime.h>
#include <cuda_fp16.h>
#include <cstdint>
#include <cstddef>

#define BSZ  1024
#define HD   1024
#define VOUT 50000
#define VINP 32000
#define SRCN 256

#define BM 128
#define BN 128
#define BK 64
#define NCH (HD / BK)            // 16 K-chunks
#define NSTAGE 2

// smem rows padded to 144B (36 words): 8-row LDSM hits all 32 banks once
#define ROWB 144
#define TILEB (128 * ROWB)       // 18432 B per tile
#define OFF_A 0
#define OFF_B (TILEB)
#define STAGE_BYTES (2 * TILEB)  // 36864
#define SMEM_TOTAL (NSTAGE * STAGE_BYTES)

// ---------------- scratch (static device globals) ---------------------------
__device__ __half g_Wf[(size_t)VOUT * HD];
__device__ __half g_Xf[(size_t)BSZ * HD];
__device__ float g_b2[VOUT];
__device__ float g_G [(size_t)BSZ * VOUT];          // gen_scores -> out_scores
__device__ int   g_sel[VOUT];
__device__ int   g_win[VINP];

// ---------------- PTX helpers ------------------------------------------------
__device__ __forceinline__ uint32_t smem_u32(const void* p) {
    uint32_t a;
    asm("{ .reg .u64 t; cvta.to.shared.u64 t, %1; cvt.u32.u64 %0, t; }"
        : "=r"(a) : "l"(p));
    return a;
}

__device__ __forceinline__ void cp16(uint32_t dst, const void* src, int nbytes) {
    asm volatile("cp.async.cg.shared.global [%0], [%1], 16, %2;"
                 :: "r"(dst), "l"(src), "r"(nbytes) : "memory");
}
#define CP_COMMIT() asm volatile("cp.async.commit_group;" ::: "memory")
#define CP_WAIT(n)  asm volatile("cp.async.wait_group %0;" :: "n"(n) : "memory")

__device__ __forceinline__ void ldsm4(uint32_t* r, uint32_t addr) {
    asm volatile("ldmatrix.sync.aligned.m8n8.x4.shared.b16 {%0,%1,%2,%3}, [%4];"
                 : "=r"(r[0]), "=r"(r[1]), "=r"(r[2]), "=r"(r[3]) : "r"(addr));
}

__device__ __forceinline__ void mma_fp16(float* d, const uint32_t* a, const uint32_t* b) {
    asm volatile("mma.sync.aligned.m16n8k16.row.col.f32.f16.f16.f32 "
                 "{%0,%1,%2,%3}, {%4,%5,%6,%7}, {%8,%9}, {%0,%1,%2,%3};"
                 : "+f"(d[0]), "+f"(d[1]), "+f"(d[2]), "+f"(d[3])
                 : "r"(a[0]), "r"(a[1]), "r"(a[2]), "r"(a[3]),
                   "r"(b[0]), "r"(b[1]));
}

// ---------------- small prep kernels ----------------------------------------
__global__ void k_sel_init() {
    int i = blockIdx.x * 256 + threadIdx.x;
    if (i < VOUT) g_sel[i] = -1;
}
__global__ void k_sel_max(const int* __restrict__ i2a) {
    int i = blockIdx.x * 256 + threadIdx.x;
    if (i < VINP) atomicMax(&g_sel[i2a[i]], i);
}
__global__ void k_win_build(const int* __restrict__ i2a) {
    int i = blockIdx.x * 256 + threadIdx.x;
    if (i < VINP) {
        int a = i2a[i];
        g_win[i] = (g_sel[a] == i) ? a : -1;
    }
}

// permute W rows + convert fp32 -> fp16
__global__ void k_prep_w(const float* __restrict__ W, const float* __restrict__ bias,
                         const int* __restrict__ omap) {
    int j  = blockIdx.x;
    int om = omap[j];
    float4 v = ((const float4*)(W + (size_t)om * HD))[threadIdx.x];
    size_t o = (size_t)j * HD + threadIdx.x * 4;
    ((__half2*)(g_Wf + o))[0] = __floats2half2_rn(v.x, v.y);
    ((__half2*)(g_Wf + o))[1] = __floats2half2_rn(v.z, v.w);
    if (threadIdx.x == 0) g_b2[j] = bias[om];
}

__global__ void k_prep_x(const float* __restrict__ X) {
    int m = blockIdx.x;
    float4 v = ((const float4*)(X + (size_t)m * HD))[threadIdx.x];
    size_t o = (size_t)m * HD + threadIdx.x * 4;
    ((__half2*)(g_Xf + o))[0] = __floats2half2_rn(v.x, v.y);
    ((__half2*)(g_Xf + o))[1] = __floats2half2_rn(v.z, v.w);
}

// ---------------- mma.sync GEMM ----------------------------------------------
__device__ __forceinline__ void issue_stage(uint32_t sb, int stage, int kc,
                                            int m0, int n0, int tid) {
    uint32_t base = sb + stage * STAGE_BYTES;
    for (int i = tid; i < 1024; i += 256) {    // 128 rows * 8 16B-segments
        int r = i >> 3, s = i & 7;
        uint32_t doff = r * ROWB + s * 16;
        size_t asrc = (size_t)(m0 + r) * HD + kc * BK + s * 8;
        cp16(base + OFF_A + doff, g_Xf + asrc, 16);
        int nr = n0 + r;
        int p  = (nr < VOUT) ? 16 : 0;         // 0 -> cp.async zero-fills
        size_t bsrc = (size_t)(nr < VOUT ? nr : (VOUT - 1)) * HD + kc * BK + s * 8;
        cp16(base + OFF_B + doff, g_Wf + bsrc, p);
    }
}

__global__ __launch_bounds__(256, 2)
void k_gemm(const int* __restrict__ mask, float* __restrict__ out2) {
    extern __shared__ char smem[];
    uint32_t sb = smem_u32(smem);
    const int tid  = threadIdx.x;
    const int wid  = tid >> 5;
    const int lane = tid & 31;
    const int wm   = wid >> 1;          // 0..3 -> m
    const int wn   = wid & 1;           // 0..1 -> n
    const int m0   = blockIdx.x * BM;   // 8 m-tiles, fastest -> W reuse in L2
    const int n0   = blockIdx.y * BN;   // 391 n-tiles

    float acc[2][8][4];
#pragma unroll
    for (int i = 0; i < 2; ++i)
#pragma unroll
        for (int j = 0; j < 8; ++j)
#pragma unroll
            for (int q2 = 0; q2 < 4; ++q2) acc[i][j][q2] = 0.f;

    issue_stage(sb, 0, 0, m0, n0, tid);
    CP_COMMIT();

    // ldmatrix per-lane address offsets
    const int q    = lane >> 3;
    const int rsel = lane & 7;
    // A x4 tiles: (r,k0),(r+8,k0),(r,k0+8),(r+8,k0+8)
    const uint32_t a_off = (uint32_t)((wm * 32 + rsel + ((q & 1) << 3)) * ROWB + (q >> 1) * 16);
    // B x4 tiles: (j,k0),(j,k8),(j+1,k0),(j+1,k8)
    const uint32_t b_off = (uint32_t)((wn * 64 + rsel + ((q >> 1) << 3)) * ROWB + (q & 1) * 16);

    const int lr = lane >> 2;          // 0..7  (epilogue)
    const int lc = (lane & 3) * 2;     // 0,2,4,6

    uint32_t Afr[2][2][4];             // [kk&1][i][4]
    uint32_t Bt [2][4];                // [t&1][4]

    for (int c = 0; c < NCH; ++c) {
        int s = c & 1;
        CP_WAIT(0);
        __syncthreads();               // orders compute(c-1) reads before overwrite
        if (c + 1 < NCH) {
            issue_stage(sb, s ^ 1, c + 1, m0, n0, tid);
            CP_COMMIT();
        }

        uint32_t stb = sb + s * STAGE_BYTES;
        uint32_t aA = stb + OFF_A + a_off;
        uint32_t aB = stb + OFF_B + b_off;

        // preload fragments for t=0 (kk=0, jp=0)
        ldsm4(Afr[0][0], aA);
        ldsm4(Afr[0][1], aA + 16 * ROWB);
        ldsm4(Bt[0], aB);

        // 16 steps: t = kk*4 + jp.  Prefetch t+1's B (and next kk's A) before
        // issuing t's MMAs -> every LDSM gets ~4 MMA latencies of slack.
#pragma unroll
        for (int t = 0; t < 16; ++t) {
            const int kk = t >> 2, jp = t & 3;
            const int cb = t & 1, nb = cb ^ 1;
            if (t + 1 < 16) {
                const int t1 = t + 1;
                ldsm4(Bt[nb], aB + (uint32_t)((t1 >> 2) * 32 + (t1 & 3) * 16 * ROWB));
            }
            if (jp == 0 && kk + 1 < 4) {
                uint32_t aAn = aA + (uint32_t)((kk + 1) * 32);
                ldsm4(Afr[(kk + 1) & 1][0], aAn);
                ldsm4(Afr[(kk + 1) & 1][1], aAn + 16 * ROWB);
            }
            const uint32_t* A0 = Afr[kk & 1][0];
            const uint32_t* A1 = Afr[kk & 1][1];
            mma_fp16(acc[0][jp * 2    ], A0, Bt[cb]    );
            mma_fp16(acc[1][jp * 2    ], A1, Bt[cb]    );
            mma_fp16(acc[0][jp * 2 + 1], A0, Bt[cb] + 2);
            mma_fp16(acc[1][jp * 2 + 1], A1, Bt[cb] + 2);
        }
    }

    // epilogue: bias add, write G and gen_masked
#pragma unroll
    for (int i = 0; i < 2; ++i) {
        int r0 = m0 + wm * 32 + i * 16 + lr;
#pragma unroll
        for (int j = 0; j < 8; ++j) {
            int n = n0 + wn * 64 + j * 8 + lc;
            if (n < VOUT) {
                float2 bb = *(const float2*)(g_b2 + n);
                float gx = acc[i][j][0] + bb.x;
                float gy = acc[i][j][1] + bb.y;
                size_t o0 = (size_t)r0 * VOUT + n;
                *(float2*)(g_G + o0) = make_float2(gx, gy);
                int2 mk0 = *(const int2*)(mask + o0);
                *(float2*)(out2 + o0) =
                    make_float2(gx - 1.0e6f * (float)mk0.x, gy - 1.0e6f * (float)mk0.y);

                float gz = acc[i][j][2] + bb.x;
                float gw = acc[i][j][3] + bb.y;
                size_t o1 = (size_t)(r0 + 8) * VOUT + n;
                *(float2*)(g_G + o1) = make_float2(gz, gw);
                int2 mk1 = *(const int2*)(mask + o1);
                *(float2*)(out2 + o1) =
                    make_float2(gz - 1.0e6f * (float)mk1.x, gw - 1.0e6f * (float)mk1.y);
            }
        }
    }
}

// ---------------- fused scatter + softmax (block b owns row b) ---------------
__global__ void k_softmax(float* __restrict__ out1,
                          const float* __restrict__ attn,
                          const int* __restrict__ ctx) {
    int b = blockIdx.x;
    // scatter pointer scores for row b (only this block touches row b)
    if (threadIdx.x < SRCN) {
        int v = ctx[b * SRCN + threadIdx.x];
        int o = g_win[v];
        if (o >= 0) atomicAdd(g_G + (size_t)b * VOUT + o, attn[b * SRCN + threadIdx.x]);
    }
    __syncthreads();   // atomics L2-visible; no thread read row b before this

    const float4* Gr = (const float4*)(g_G + (size_t)b * VOUT);
    float m = -3.4e38f, s = 0.f;
    for (int i = threadIdx.x; i < VOUT / 4; i += blockDim.x) {
        float4 v = Gr[i];
#define ONL(x)                                                   \
        if ((x) > m) { s = s * __expf(m - (x)) + 1.f; m = (x); } \
        else         { s += __expf((x) - m); }
        ONL(v.x) ONL(v.y) ONL(v.z) ONL(v.w)
#undef ONL
    }
    __shared__ float sm[256], ss[256];
    sm[threadIdx.x] = m;
    ss[threadIdx.x] = s;
    __syncthreads();
    for (int off = 128; off; off >>= 1) {
        if (threadIdx.x < off) {
            float m1 = sm[threadIdx.x], s1 = ss[threadIdx.x];
            float m2 = sm[threadIdx.x + off], s2 = ss[threadIdx.x + off];
            float M = fmaxf(m1, m2);
            sm[threadIdx.x] = M;
            ss[threadIdx.x] = s1 * __expf(m1 - M) + s2 * __expf(m2 - M);
        }
        __syncthreads();
    }
    float rm  = sm[0];
    float inv = 1.f / ss[0];
    float4* Or = (float4*)(out1 + (size_t)b * VOUT);
    for (int i = threadIdx.x; i < VOUT / 4; i += blockDim.x) {
        float4 v = Gr[i];                           // L2-resident re-read
        float4 o;
        o.x = __expf(v.x - rm) * inv;
        o.y = __expf(v.y - rm) * inv;
        o.z = __expf(v.z - rm) * inv;
        o.w = __expf(v.w - rm) * inv;
        Or[i] = o;
    }
}

// ---------------- launch ----------------------------------------------------
extern "C" void kernel_launch(void* const* d_in, const int* in_sizes, int n_in,
                              void* d_out, int out_size) {
    const float* x    = (const float*)d_in[0];
    const float* W    = (const float*)d_in[1];
    const float* bv   = (const float*)d_in[2];
    const float* attn = (const float*)d_in[3];
    const int*   ctx  = (const int*)d_in[4];
    const int*   i2a  = (const int*)d_in[5];
    const int*   omap = (const int*)d_in[6];
    const int*   mask = (const int*)d_in[7];

    float* out1 = (float*)d_out;                       // out_probs  [B, VOUT]
    float* out2 = out1 + (size_t)BSZ * VOUT;           // gen_masked [B, VOUT]

    cudaFuncSetAttribute(k_gemm, cudaFuncAttributeMaxDynamicSharedMemorySize, SMEM_TOTAL);

    // Order keeps k_gemm in ncu's captured slot (4th launch).
    k_prep_w<<<VOUT, 256>>>(W, bv, omap);              // 1
    k_prep_x<<<BSZ, 256>>>(x);                         // 2
    k_sel_init<<<(VOUT + 255) / 256, 256>>>();         // 3

    dim3 ggrid(BSZ / BM, (VOUT + BN - 1) / BN);        // 8 x 391, m fastest
    k_gemm<<<ggrid, 256, SMEM_TOTAL>>>(mask, out2);    // 4  <- profiled

    k_sel_max  <<<(VINP + 255) / 256, 256>>>(i2a);     // 5
    k_win_build<<<(VINP + 255) / 256, 256>>>(i2a);     // 6

    k_softmax<<<BSZ, 256>>>(out1, attn, ctx);          // scatter fused in
}